// round 15
// baseline (speedup 1.0000x reference)
#include <cuda_runtime.h>
#include <cuda_fp16.h>

#define N_NODES   50000
#define N_EDGES   800000
#define F_IN      16
#define F_EDGE    8
#define H         8
#define NUM_GRAPHS 512

#define TPB    256
#define NBLK   1184                 // 148 SMs x 8 blocks; single wave on GB300 (152 SMs)
#define STRIDE (TPB * NBLK)

// Q (o-major, fp16): Q[n][j*8+f], row = 64 halves = 128 B, line-aligned.
__device__ __align__(128) __half g_Qh[N_NODES * 64];       // 6.4 MB
__device__ __align__(16)  float  g_bias[N_NODES * H];      // 1.6 MB
__device__ __align__(16)  float  g_agg1[N_NODES * H];      // 1.6 MB
__device__ __align__(16)  float  g_agg2[N_NODES * H];      // 1.6 MB

// Grid barrier state. Generation counter only ever increments; no per-launch
// reset needed (spinners compare against the value they read on entry).
__device__ unsigned g_barCount;
__device__ unsigned g_barGen;

__device__ __forceinline__ void grid_barrier() {
    __syncthreads();
    if (threadIdx.x == 0) {
        __threadfence();
        unsigned my = *(volatile unsigned*)&g_barGen;
        if (atomicAdd(&g_barCount, 1u) + 1u == (unsigned)gridDim.x) {
            atomicExch(&g_barCount, 0u);
            __threadfence();
            atomicAdd(&g_barGen, 1u);
        } else {
            while (*(volatile unsigned*)&g_barGen == my) __nanosleep(32);
        }
        __threadfence();
    }
    __syncthreads();
}

// Edge pass body (R4-proven): 8 lanes per edge, fp16 Q single-line gather,
// scalar fp32 atomicAdd.
__device__ __forceinline__ void edge_phase(const int* __restrict__ ei,
                                           const float* __restrict__ ea,
                                           float* __restrict__ agg, int tg) {
    for (int idx = tg; idx < N_EDGES * 8; idx += STRIDE) {
        int e = idx >> 3, j = idx & 7;
        int s = __ldg(&ei[e]);
        int d = __ldg(&ei[N_EDGES + e]);

        const float4* eap = (const float4*)(ea + e * 8);
        float4 a0 = __ldg(eap);
        float4 a1 = __ldg(eap + 1);

        uint4 qraw = __ldg((const uint4*)(g_Qh + s * 64 + j * 8));
        union { uint4 u; __half2 h[4]; } qk; qk.u = qraw;
        float2 f0 = __half22float2(qk.h[0]);
        float2 f1 = __half22float2(qk.h[1]);
        float2 f2 = __half22float2(qk.h[2]);
        float2 f3 = __half22float2(qk.h[3]);

        float r = __ldg(&g_bias[s * 8 + j]);
        r = fmaf(a0.x, f0.x, r);
        r = fmaf(a0.y, f0.y, r);
        r = fmaf(a0.z, f1.x, r);
        r = fmaf(a0.w, f1.y, r);
        r = fmaf(a1.x, f2.x, r);
        r = fmaf(a1.y, f2.y, r);
        r = fmaf(a1.z, f3.x, r);
        r = fmaf(a1.w, f3.y, r);

        atomicAdd(&agg[d * 8 + j], r);
    }
}

__device__ __forceinline__ int lower_bound_batch(const int* __restrict__ batch, int key) {
    int lo = 0, hi = N_NODES;
    while (lo < hi) {
        int mid = (lo + hi) >> 1;
        if (__ldg(&batch[mid]) < key) lo = mid + 1;
        else hi = mid;
    }
    return lo;
}

// ---------------------------------------------------------------------------
// One persistent kernel: node1 | edge1 | node2 | edge2 | pool+readout,
// separated by grid barriers. Inner bodies identical to the proven R4/R12.
// ---------------------------------------------------------------------------
__global__ void __launch_bounds__(TPB, 8) fused_kernel(
    const float* __restrict__ x,     const int* __restrict__ ei,
    const float* __restrict__ ea,    const int* __restrict__ batch,
    const float* __restrict__ We1,   const float* __restrict__ be1,
    const float* __restrict__ root1, const float* __restrict__ b1,
    const float* __restrict__ We2,   const float* __restrict__ be2,
    const float* __restrict__ root2, const float* __restrict__ b2,
    const float* __restrict__ Wlast, const float* __restrict__ blast,
    float* __restrict__ out)
{
    __shared__ float sW1[F_EDGE * F_IN * H];   // 1024
    __shared__ float sR1[F_IN * H];            // 128
    __shared__ float sB1[F_IN * H];            // 128
    __shared__ float sb1[H];
    __shared__ float sW2[F_EDGE * H * H];      // 512
    __shared__ float sR2[H * H];               // 64
    __shared__ float sB2[H * H];               // 64
    __shared__ float sb2[H];
    __shared__ float s_warp[TPB / 32];
    __shared__ int   s_range[2];

    // Load ALL weights once.
    for (int i = threadIdx.x; i < F_EDGE * F_IN * H; i += TPB) sW1[i] = We1[i];
    for (int i = threadIdx.x; i < F_IN * H; i += TPB) { sR1[i] = root1[i]; sB1[i] = be1[i]; }
    for (int i = threadIdx.x; i < F_EDGE * H * H; i += TPB) sW2[i] = We2[i];
    for (int i = threadIdx.x; i < H * H; i += TPB) { sR2[i] = root2[i]; sB2[i] = be2[i]; }
    if (threadIdx.x < H) { sb1[threadIdx.x] = b1[threadIdx.x]; sb2[threadIdx.x] = b2[threadIdx.x]; }
    __syncthreads();

    int tg = blockIdx.x * TPB + threadIdx.x;

    // ---- Phase 1: node1 precompute ----
    for (int idx = tg; idx < N_NODES * 8; idx += STRIDE) {
        int n = idx >> 3, j = idx & 7;
        float xv[F_IN];
        const float4* xp = (const float4*)(x + n * F_IN);
        #pragma unroll
        for (int v = 0; v < 4; v++) {
            float4 t = __ldg(xp + v);
            xv[v * 4 + 0] = t.x; xv[v * 4 + 1] = t.y; xv[v * 4 + 2] = t.z; xv[v * 4 + 3] = t.w;
        }
        float q[8];
        #pragma unroll
        for (int f = 0; f < 8; f++) {
            float s = 0.f;
            #pragma unroll
            for (int i = 0; i < F_IN; i++) s = fmaf(xv[i], sW1[f * 128 + i * 8 + j], s);
            q[f] = s;
        }
        union { uint4 u; __half2 h[4]; } pk;
        pk.h[0] = __floats2half2_rn(q[0], q[1]);
        pk.h[1] = __floats2half2_rn(q[2], q[3]);
        pk.h[2] = __floats2half2_rn(q[4], q[5]);
        pk.h[3] = __floats2half2_rn(q[6], q[7]);
        *(uint4*)(g_Qh + n * 64 + j * 8) = pk.u;

        float qb = 0.f, r = sb1[j];
        #pragma unroll
        for (int i = 0; i < F_IN; i++) {
            qb = fmaf(xv[i], sB1[i * 8 + j], qb);
            r  = fmaf(xv[i], sR1[i * 8 + j], r);
        }
        g_bias[n * 8 + j] = qb;
        g_agg1[n * 8 + j] = r;
    }
    grid_barrier();

    // ---- Phase 2: edge pass layer 1 ----
    edge_phase(ei, ea, g_agg1, tg);
    grid_barrier();

    // ---- Phase 3: node2 precompute ----
    for (int idx = tg; idx < N_NODES * 8; idx += STRIDE) {
        int n = idx >> 3, j = idx & 7;
        float h[H];
        const float4* hp = (const float4*)(g_agg1 + n * 8);
        float4 a0 = hp[0], a1 = hp[1];
        h[0] = fmaxf(a0.x, 0.f); h[1] = fmaxf(a0.y, 0.f);
        h[2] = fmaxf(a0.z, 0.f); h[3] = fmaxf(a0.w, 0.f);
        h[4] = fmaxf(a1.x, 0.f); h[5] = fmaxf(a1.y, 0.f);
        h[6] = fmaxf(a1.z, 0.f); h[7] = fmaxf(a1.w, 0.f);

        float q[8];
        #pragma unroll
        for (int f = 0; f < 8; f++) {
            float s = 0.f;
            #pragma unroll
            for (int i = 0; i < H; i++) s = fmaf(h[i], sW2[f * 64 + i * 8 + j], s);
            q[f] = s;
        }
        union { uint4 u; __half2 hh[4]; } pk;
        pk.hh[0] = __floats2half2_rn(q[0], q[1]);
        pk.hh[1] = __floats2half2_rn(q[2], q[3]);
        pk.hh[2] = __floats2half2_rn(q[4], q[5]);
        pk.hh[3] = __floats2half2_rn(q[6], q[7]);
        *(uint4*)(g_Qh + n * 64 + j * 8) = pk.u;

        float qb = 0.f, r = sb2[j];
        #pragma unroll
        for (int i = 0; i < H; i++) {
            qb = fmaf(h[i], sB2[i * 8 + j], qb);
            r  = fmaf(h[i], sR2[i * 8 + j], r);
        }
        g_bias[n * 8 + j] = qb;
        g_agg2[n * 8 + j] = r;
    }
    grid_barrier();

    // ---- Phase 4: edge pass layer 2 ----
    edge_phase(ei, ea, g_agg2, tg);
    grid_barrier();

    // ---- Phase 5: pool + readout (block g = graph g; batch sorted) ----
    if (blockIdx.x < NUM_GRAPHS) {
        int g = blockIdx.x;
        if (threadIdx.x == 0)       s_range[0] = lower_bound_batch(batch, g);
        else if (threadIdx.x == 32) s_range[1] = lower_bound_batch(batch, g + 1);
        __syncthreads();
        int start = s_range[0], end = s_range[1];

        float w[8];
        #pragma unroll
        for (int c = 0; c < 8; c++) w[c] = __ldg(&Wlast[c]);

        float v = 0.f;
        for (int n = start + threadIdx.x; n < end; n += TPB) {
            const float4* ap = (const float4*)(g_agg2 + n * 8);
            float4 a0 = ap[0], a1 = ap[1];
            v = fmaf(fmaxf(a0.x, 0.f), w[0], v);
            v = fmaf(fmaxf(a0.y, 0.f), w[1], v);
            v = fmaf(fmaxf(a0.z, 0.f), w[2], v);
            v = fmaf(fmaxf(a0.w, 0.f), w[3], v);
            v = fmaf(fmaxf(a1.x, 0.f), w[4], v);
            v = fmaf(fmaxf(a1.y, 0.f), w[5], v);
            v = fmaf(fmaxf(a1.z, 0.f), w[6], v);
            v = fmaf(fmaxf(a1.w, 0.f), w[7], v);
        }
        #pragma unroll
        for (int off = 16; off >= 1; off >>= 1)
            v += __shfl_xor_sync(0xffffffffu, v, off, 32);
        if ((threadIdx.x & 31) == 0) s_warp[threadIdx.x >> 5] = v;
        __syncthreads();
        if (threadIdx.x == 0) {
            float t = 0.f;
            #pragma unroll
            for (int wi = 0; wi < TPB / 32; wi++) t += s_warp[wi];
            out[g] = t + __ldg(&blast[0]);
        }
    }
}

// ---------------------------------------------------------------------------
extern "C" void kernel_launch(void* const* d_in, const int* in_sizes, int n_in,
                              void* d_out, int out_size) {
    const float* x     = (const float*)d_in[0];
    const int*   ei    = (const int*)  d_in[1];
    const float* ea    = (const float*)d_in[2];
    const int*   batch = (const int*)  d_in[3];
    const float* We1   = (const float*)d_in[4];
    const float* be1   = (const float*)d_in[5];
    const float* root1 = (const float*)d_in[6];
    const float* b1    = (const float*)d_in[7];
    const float* We2   = (const float*)d_in[8];
    const float* be2   = (const float*)d_in[9];
    const float* root2 = (const float*)d_in[10];
    const float* b2    = (const float*)d_in[11];
    const float* Wlast = (const float*)d_in[12];
    const float* blast = (const float*)d_in[13];
    float* out = (float*)d_out;

    fused_kernel<<<NBLK, TPB>>>(x, ei, ea, batch,
                                We1, be1, root1, b1,
                                We2, be2, root2, b2,
                                Wlast, blast, out);
}

// round 16
// speedup vs baseline: 1.7738x; 1.7738x over previous
#include <cuda_runtime.h>
#include <cuda_fp16.h>

#define N_NODES   50000
#define N_EDGES   800000
#define F_IN      16
#define F_EDGE    8
#define H         8
#define NUM_GRAPHS 512

// Q (o-major, fp16): Q[n][j*8+f], row = 64 halves = 128 B, line-aligned.
__device__ __align__(128) __half g_Qh[N_NODES * 64];       // 6.4 MB
__device__ __align__(16)  float  g_bias[N_NODES * H];      // 1.6 MB  (x@Be per node)
__device__ __align__(16)  float  g_agg1[N_NODES * H];      // 1.6 MB
__device__ __align__(16)  float  g_agg2[N_NODES * H];      // 1.6 MB
// ea packed to fp16 once (in node1), read by BOTH edge passes as one uint4.
__device__ __align__(16)  __half g_ea16[N_EDGES * 8];      // 12.8 MB

// ---------------------------------------------------------------------------
// Layer-1 node precompute (8 lanes per node, lane j = output channel j):
//   Qh[n][j*8+f] = sum_i x[n,i]*We1[f, i*8+j]    (fp16, o-major)
//   bias[n][j]   = sum_i x[n,i]*be1[i*8+j]
//   agg1[n][j]   = x[n]@root1[:,j] + b1[j]
// Plus: fused grid-stride prepack of ea -> fp16 (amortized over 2 edge passes).
// ---------------------------------------------------------------------------
__global__ void node1_kernel(const float* __restrict__ x,
                             const float* __restrict__ We1,
                             const float* __restrict__ be1,
                             const float* __restrict__ root1,
                             const float* __restrict__ b1,
                             const float* __restrict__ ea) {
    __shared__ float sW[F_EDGE * F_IN * H];
    __shared__ float sR[F_IN * H];
    __shared__ float sB[F_IN * H];
    __shared__ float sb[H];
    for (int i = threadIdx.x; i < F_EDGE * F_IN * H; i += blockDim.x) sW[i] = We1[i];
    for (int i = threadIdx.x; i < F_IN * H; i += blockDim.x) { sR[i] = root1[i]; sB[i] = be1[i]; }
    if (threadIdx.x < H) sb[threadIdx.x] = b1[threadIdx.x];
    __syncthreads();

    int gid = blockIdx.x * blockDim.x + threadIdx.x;
    int stride = gridDim.x * blockDim.x;

    // ---- ea -> fp16 prepack (independent of node work) ----
    for (int e = gid; e < N_EDGES; e += stride) {
        const float4* eap = (const float4*)(ea + e * 8);
        float4 a0 = __ldg(eap);
        float4 a1 = __ldg(eap + 1);
        union { uint4 u; __half2 h[4]; } pk;
        pk.h[0] = __floats2half2_rn(a0.x, a0.y);
        pk.h[1] = __floats2half2_rn(a0.z, a0.w);
        pk.h[2] = __floats2half2_rn(a1.x, a1.y);
        pk.h[3] = __floats2half2_rn(a1.z, a1.w);
        *(uint4*)(g_ea16 + e * 8) = pk.u;
    }

    int n = gid >> 3, j = gid & 7;
    if (n >= N_NODES) return;

    float xv[F_IN];
    const float4* xp = (const float4*)(x + n * F_IN);
    #pragma unroll
    for (int v = 0; v < 4; v++) {
        float4 t = __ldg(xp + v);
        xv[v * 4 + 0] = t.x; xv[v * 4 + 1] = t.y; xv[v * 4 + 2] = t.z; xv[v * 4 + 3] = t.w;
    }

    float q[8];
    #pragma unroll
    for (int f = 0; f < 8; f++) {
        float s = 0.f;
        #pragma unroll
        for (int i = 0; i < F_IN; i++) s = fmaf(xv[i], sW[f * 128 + i * 8 + j], s);
        q[f] = s;
    }
    union { uint4 u; __half2 h[4]; } pk;
    pk.h[0] = __floats2half2_rn(q[0], q[1]);
    pk.h[1] = __floats2half2_rn(q[2], q[3]);
    pk.h[2] = __floats2half2_rn(q[4], q[5]);
    pk.h[3] = __floats2half2_rn(q[6], q[7]);
    *(uint4*)(g_Qh + n * 64 + j * 8) = pk.u;

    float qb = 0.f, r = sb[j];
    #pragma unroll
    for (int i = 0; i < F_IN; i++) {
        qb = fmaf(xv[i], sB[i * 8 + j], qb);
        r  = fmaf(xv[i], sR[i * 8 + j], r);
    }
    g_bias[n * 8 + j] = qb;
    g_agg1[n * 8 + j] = r;
}

// ---------------------------------------------------------------------------
// Layer-2 node precompute: h = relu(agg1); same structure
// ---------------------------------------------------------------------------
__global__ void node2_kernel(const float* __restrict__ We2,
                             const float* __restrict__ be2,
                             const float* __restrict__ root2,
                             const float* __restrict__ b2) {
    __shared__ float sW[F_EDGE * H * H];
    __shared__ float sR[H * H];
    __shared__ float sB[H * H];
    __shared__ float sb[H];
    for (int i = threadIdx.x; i < F_EDGE * H * H; i += blockDim.x) sW[i] = We2[i];
    for (int i = threadIdx.x; i < H * H; i += blockDim.x) { sR[i] = root2[i]; sB[i] = be2[i]; }
    if (threadIdx.x < H) sb[threadIdx.x] = b2[threadIdx.x];
    __syncthreads();

    int gid = blockIdx.x * blockDim.x + threadIdx.x;
    int n = gid >> 3, j = gid & 7;
    if (n >= N_NODES) return;

    float h[H];
    const float4* hp = (const float4*)(g_agg1 + n * 8);
    float4 a0 = hp[0], a1 = hp[1];
    h[0] = fmaxf(a0.x, 0.f); h[1] = fmaxf(a0.y, 0.f);
    h[2] = fmaxf(a0.z, 0.f); h[3] = fmaxf(a0.w, 0.f);
    h[4] = fmaxf(a1.x, 0.f); h[5] = fmaxf(a1.y, 0.f);
    h[6] = fmaxf(a1.z, 0.f); h[7] = fmaxf(a1.w, 0.f);

    float q[8];
    #pragma unroll
    for (int f = 0; f < 8; f++) {
        float s = 0.f;
        #pragma unroll
        for (int i = 0; i < H; i++) s = fmaf(h[i], sW[f * 64 + i * 8 + j], s);
        q[f] = s;
    }
    union { uint4 u; __half2 hh[4]; } pk;
    pk.hh[0] = __floats2half2_rn(q[0], q[1]);
    pk.hh[1] = __floats2half2_rn(q[2], q[3]);
    pk.hh[2] = __floats2half2_rn(q[4], q[5]);
    pk.hh[3] = __floats2half2_rn(q[6], q[7]);
    *(uint4*)(g_Qh + n * 64 + j * 8) = pk.u;

    float qb = 0.f, r = sb[j];
    #pragma unroll
    for (int i = 0; i < H; i++) {
        qb = fmaf(h[i], sB[i * 8 + j], qb);
        r  = fmaf(h[i], sR[i * 8 + j], r);
    }
    g_bias[n * 8 + j] = qb;
    g_agg2[n * 8 + j] = r;
}

// ---------------------------------------------------------------------------
// Edge pass (R4-proven core): 8 lanes per edge, 2 edges per thread,
// fp16 Q single-line gather, fp16 ea single-uint4 load, scalar fp32 atomicAdd.
// ---------------------------------------------------------------------------
#define EPT 2
#define HALF_E (N_EDGES / EPT)

template <int LAYER>
__global__ void __launch_bounds__(256) edge_kernel(const int* __restrict__ ei) {
    int gid = blockIdx.x * blockDim.x + threadIdx.x;
    int e0 = gid >> 3, j = gid & 7;
    float* agg = LAYER ? g_agg2 : g_agg1;

    #pragma unroll
    for (int k = 0; k < EPT; k++) {
        int e = e0 + k * HALF_E;
        int s = __ldg(&ei[e]);
        int d = __ldg(&ei[N_EDGES + e]);

        uint4 eraw = __ldg((const uint4*)(g_ea16 + e * 8));
        union { uint4 u; __half2 h[4]; } ek; ek.u = eraw;
        float2 a0 = __half22float2(ek.h[0]);
        float2 a1 = __half22float2(ek.h[1]);
        float2 a2 = __half22float2(ek.h[2]);
        float2 a3 = __half22float2(ek.h[3]);

        uint4 qraw = __ldg((const uint4*)(g_Qh + s * 64 + j * 8));
        union { uint4 u; __half2 h[4]; } qk; qk.u = qraw;
        float2 f0 = __half22float2(qk.h[0]);
        float2 f1 = __half22float2(qk.h[1]);
        float2 f2 = __half22float2(qk.h[2]);
        float2 f3 = __half22float2(qk.h[3]);

        float r = __ldg(&g_bias[s * 8 + j]);
        r = fmaf(a0.x, f0.x, r);
        r = fmaf(a0.y, f0.y, r);
        r = fmaf(a1.x, f1.x, r);
        r = fmaf(a1.y, f1.y, r);
        r = fmaf(a2.x, f2.x, r);
        r = fmaf(a2.y, f2.y, r);
        r = fmaf(a3.x, f3.x, r);
        r = fmaf(a3.y, f3.y, r);

        atomicAdd(&agg[d * 8 + j], r);
    }
}

// ---------------------------------------------------------------------------
// Fused pool + readout, no atomics (batch sorted; block g = graph g).
// ---------------------------------------------------------------------------
#define FIN_TPB 128

__device__ __forceinline__ int lower_bound_batch(const int* __restrict__ batch, int key) {
    int lo = 0, hi = N_NODES;
    while (lo < hi) {
        int mid = (lo + hi) >> 1;
        if (__ldg(&batch[mid]) < key) lo = mid + 1;
        else hi = mid;
    }
    return lo;
}

__global__ void __launch_bounds__(FIN_TPB) final_kernel(const int* __restrict__ batch,
                                                        const float* __restrict__ Wlast,
                                                        const float* __restrict__ blast,
                                                        float* __restrict__ out) {
    int g = blockIdx.x;
    __shared__ int s_range[2];
    __shared__ float s_warp[FIN_TPB / 32];

    if (threadIdx.x == 0)       s_range[0] = lower_bound_batch(batch, g);
    else if (threadIdx.x == 32) s_range[1] = lower_bound_batch(batch, g + 1);
    __syncthreads();
    int start = s_range[0], end = s_range[1];

    float w[8];
    #pragma unroll
    for (int c = 0; c < 8; c++) w[c] = __ldg(&Wlast[c]);

    float v = 0.f;
    for (int n = start + threadIdx.x; n < end; n += FIN_TPB) {
        const float4* ap = (const float4*)(g_agg2 + n * 8);
        float4 a0 = ap[0], a1 = ap[1];
        v = fmaf(fmaxf(a0.x, 0.f), w[0], v);
        v = fmaf(fmaxf(a0.y, 0.f), w[1], v);
        v = fmaf(fmaxf(a0.z, 0.f), w[2], v);
        v = fmaf(fmaxf(a0.w, 0.f), w[3], v);
        v = fmaf(fmaxf(a1.x, 0.f), w[4], v);
        v = fmaf(fmaxf(a1.y, 0.f), w[5], v);
        v = fmaf(fmaxf(a1.z, 0.f), w[6], v);
        v = fmaf(fmaxf(a1.w, 0.f), w[7], v);
    }

    #pragma unroll
    for (int off = 16; off >= 1; off >>= 1)
        v += __shfl_xor_sync(0xffffffffu, v, off, 32);
    if ((threadIdx.x & 31) == 0) s_warp[threadIdx.x >> 5] = v;
    __syncthreads();
    if (threadIdx.x == 0) {
        float t = 0.f;
        #pragma unroll
        for (int wi = 0; wi < FIN_TPB / 32; wi++) t += s_warp[wi];
        out[g] = t + __ldg(&blast[0]);
    }
}

// ---------------------------------------------------------------------------
extern "C" void kernel_launch(void* const* d_in, const int* in_sizes, int n_in,
                              void* d_out, int out_size) {
    const float* x     = (const float*)d_in[0];
    const int*   ei    = (const int*)  d_in[1];
    const float* ea    = (const float*)d_in[2];
    const int*   batch = (const int*)  d_in[3];
    const float* We1   = (const float*)d_in[4];
    const float* be1   = (const float*)d_in[5];
    const float* root1 = (const float*)d_in[6];
    const float* b1    = (const float*)d_in[7];
    const float* We2   = (const float*)d_in[8];
    const float* be2   = (const float*)d_in[9];
    const float* root2 = (const float*)d_in[10];
    const float* b2    = (const float*)d_in[11];
    const float* Wlast = (const float*)d_in[12];
    const float* blast = (const float*)d_in[13];
    float* out = (float*)d_out;

    const int TPB = 256;
    int node_blocks = (N_NODES * 8 + TPB - 1) / TPB;
    int edge_blocks = (HALF_E * 8) / TPB;           // 12500, exact

    node1_kernel<<<node_blocks, TPB>>>(x, We1, be1, root1, b1, ea);
    edge_kernel<0><<<edge_blocks, TPB>>>(ei);
    node2_kernel<<<node_blocks, TPB>>>(We2, be2, root2, b2);
    edge_kernel<1><<<edge_blocks, TPB>>>(ei);
    final_kernel<<<NUM_GRAPHS, FIN_TPB>>>(batch, Wlast, blast, out);
}